// round 1
// baseline (speedup 1.0000x reference)
#include <cuda_runtime.h>
#include <cstdint>

// Problem constants
#define BATCH    8
#define N_NODES  8192
#define CH       128     // CH_IN == CH_OUT == 128
#define NEXP     64
#define KT       32      // K-tile
#define NODES_PER_CHUNK 16
#define MAX_CHUNKS 64    // capacity 1024 nodes/expert (binomial mean 128, std ~11 -> safe)

// Scratch (no allocations allowed -> device globals)
__device__ int g_count[NEXP];
__device__ int g_offset[NEXP];
__device__ int g_sorted[N_NODES];

// ---------------------------------------------------------------------------
// Kernel 1: counting sort of node indices by expert. Single CTA, 1024 threads.
// Also auto-detects whether sel is int64 or int32 (JAX x64-off silently makes
// jnp.int64 -> int32). Reading 4096 int64 words = 32KB <= min buffer size.
// ---------------------------------------------------------------------------
__global__ void sort_nodes_kernel(const long long* __restrict__ sel64) {
    __shared__ int hist[NEXP];
    __shared__ int offs[NEXP];
    __shared__ int cursor[NEXP];
    __shared__ int is64_flag;

    int tid = threadIdx.x;
    if (tid == 0) is64_flag = 1;
    if (tid < NEXP) hist[tid] = 0;
    __syncthreads();

    // dtype detection: genuine int64 sel has all words in [0,64).
    for (int i = tid; i < N_NODES / 2; i += blockDim.x) {
        long long v = sel64[i];
        if (v < 0 || v >= NEXP) is64_flag = 0;  // benign race, same value
    }
    __syncthreads();
    const int is64 = is64_flag;
    const int* sel32 = (const int*)sel64;

    // histogram
    for (int n = tid; n < N_NODES; n += blockDim.x) {
        int e = is64 ? (int)sel64[n] : sel32[n];
        atomicAdd(&hist[e], 1);
    }
    __syncthreads();

    // exclusive prefix sum (serial over 64, cheap)
    if (tid == 0) {
        int s = 0;
        for (int e = 0; e < NEXP; e++) { offs[e] = s; s += hist[e]; }
    }
    __syncthreads();
    if (tid < NEXP) {
        cursor[tid]   = offs[tid];
        g_count[tid]  = hist[tid];
        g_offset[tid] = offs[tid];
    }
    __syncthreads();

    // scatter (order within expert irrelevant to final output)
    for (int n = tid; n < N_NODES; n += blockDim.x) {
        int e = is64 ? (int)sel64[n] : sel32[n];
        int pos = atomicAdd(&cursor[e], 1);
        g_sorted[pos] = n;
    }
}

// ---------------------------------------------------------------------------
// Kernel 2: grouped GEMM. One CTA = (expert e, chunk of 16 nodes).
// Tile: M=128 rows (16 nodes x 8 batches), N=128 outputs, K=128 (4 x KT=32).
// 256 threads, each computes an 8x8 micro-tile:
//   thread (tx,ty): node = snode[ty], rows = all 8 batches of that node,
//   output cols = tx + 16*n (strided mapping -> conflict-free Ws reads,
//   coalesced stores across the 16 tx lanes).
// ---------------------------------------------------------------------------
__global__ __launch_bounds__(256, 2)
void grouped_gemm_kernel(const float* __restrict__ x,
                         const float* __restrict__ W,
                         float* __restrict__ out) {
    const int e     = blockIdx.x;
    const int chunk = blockIdx.y;
    const int cnt   = g_count[e];
    const int nstart = chunk * NODES_PER_CHUNK;
    if (nstart >= cnt) return;
    const int base = g_offset[e];

    __shared__ int   snode[NODES_PER_CHUNK];
    __shared__ float Xs[128][KT + 1];
    __shared__ float Ws[128][KT + 1];

    const int tid = threadIdx.x;       // 0..255
    const int tx  = tid & 15;          // 0..15 -> output-col group
    const int ty  = tid >> 4;          // 0..15 -> node slot

    if (tid < NODES_PER_CHUNK)
        snode[tid] = (nstart + tid < cnt) ? g_sorted[base + nstart + tid] : -1;
    __syncthreads();

    const float* We = W + (size_t)e * CH * CH;
    float acc[8][8];
#pragma unroll
    for (int m = 0; m < 8; m++)
#pragma unroll
        for (int n = 0; n < 8; n++) acc[m][n] = 0.0f;

    for (int k0 = 0; k0 < CH; k0 += KT) {
        // ---- load tiles: 128 rows x 32 floats each, float4 per thread x4 ----
#pragma unroll
        for (int it = 0; it < 4; it++) {
            int idx = tid + it * 256;     // 0..1023
            int r   = idx >> 3;           // row 0..127
            int q   = (idx & 7) * 4;      // col offset 0,4,..,28
            int t   = r >> 3;             // node slot
            int b   = r & 7;              // batch
            int node = snode[t];
            float4 v = make_float4(0.f, 0.f, 0.f, 0.f);
            if (node >= 0)
                v = *(const float4*)(x + ((size_t)b * N_NODES + node) * CH + k0 + q);
            Xs[r][q + 0] = v.x; Xs[r][q + 1] = v.y;
            Xs[r][q + 2] = v.z; Xs[r][q + 3] = v.w;

            float4 w = *(const float4*)(We + (size_t)r * CH + k0 + q);
            Ws[r][q + 0] = w.x; Ws[r][q + 1] = w.y;
            Ws[r][q + 2] = w.z; Ws[r][q + 3] = w.w;
        }
        __syncthreads();

        // ---- compute ----
#pragma unroll 4
        for (int j = 0; j < KT; j++) {
            float av[8], bv[8];
#pragma unroll
            for (int m = 0; m < 8; m++) av[m] = Xs[ty * 8 + m][j];   // broadcast
#pragma unroll
            for (int n = 0; n < 8; n++) bv[n] = Ws[tx + 16 * n][j];  // conflict-free
#pragma unroll
            for (int m = 0; m < 8; m++)
#pragma unroll
                for (int n = 0; n < 8; n++)
                    acc[m][n] = fmaf(av[m], bv[n], acc[m][n]);
        }
        __syncthreads();
    }

    // ---- store: thread owns node snode[ty], batches m=0..7, cols tx+16n ----
    const int node = snode[ty];
    if (node < 0) return;
#pragma unroll
    for (int m = 0; m < 8; m++) {
        float* o = out + ((size_t)m * N_NODES + node) * CH;
#pragma unroll
        for (int n = 0; n < 8; n++)
            o[tx + 16 * n] = acc[m][n];
    }
}

// ---------------------------------------------------------------------------
extern "C" void kernel_launch(void* const* d_in, const int* in_sizes, int n_in,
                              void* d_out, int out_size) {
    const float*     x   = (const float*)d_in[0];
    const long long* sel = (const long long*)d_in[1];
    const float*     W   = (const float*)d_in[2];
    float*           out = (float*)d_out;

    sort_nodes_kernel<<<1, 1024>>>(sel);
    dim3 grid(NEXP, MAX_CHUNKS);
    grouped_gemm_kernel<<<grid, 256>>>(x, W, out);
}

// round 2
// speedup vs baseline: 2.0506x; 2.0506x over previous
#include <cuda_runtime.h>
#include <cstdint>

// Problem constants
#define BATCH    8
#define N_NODES  8192
#define CH       128     // CH_IN == CH_OUT == 128
#define NEXP     64
#define KT       64      // K-tile held in smem
#define NODES_PER_CHUNK 16
#define MAX_PAD  9216    // 8192 + 64*16 (per-expert round-up to 16)
#define MAX_CHK  576     // MAX_PAD / 16

// Scratch (no allocations allowed -> device globals)
__device__ int g_sorted[MAX_PAD];
__device__ int g_chunk_expert[MAX_CHK];

// ---------------------------------------------------------------------------
// Kernel 1: counting sort of node indices by expert, with per-expert regions
// padded (aligned) to multiples of 16 and filled with -1, plus a chunk->expert
// map so the GEMM grid is dense. Single CTA, 1024 threads.
// Also auto-detects int64 vs int32 sel (JAX x64-off makes jnp.int64 -> int32).
// ---------------------------------------------------------------------------
__global__ void sort_nodes_kernel(const long long* __restrict__ sel64) {
    __shared__ int hist[NEXP];
    __shared__ int offs[NEXP + 1];
    __shared__ int cursor[NEXP];
    __shared__ int is64_flag;

    int tid = threadIdx.x;
    if (tid == 0) is64_flag = 1;
    if (tid < NEXP) hist[tid] = 0;
    __syncthreads();

    // dtype detection: genuine int64 sel has all words in [0,64).
    for (int i = tid; i < N_NODES / 2; i += blockDim.x) {
        long long v = sel64[i];
        if (v < 0 || v >= NEXP) is64_flag = 0;  // benign race, same value
    }
    __syncthreads();
    const int is64 = is64_flag;
    const int* sel32 = (const int*)sel64;

    for (int n = tid; n < N_NODES; n += blockDim.x) {
        int e = is64 ? (int)sel64[n] : sel32[n];
        atomicAdd(&hist[e], 1);
    }
    // init padded array / chunk map while histogram settles elsewhere
    for (int i = tid; i < MAX_PAD; i += blockDim.x) g_sorted[i] = -1;
    for (int i = tid; i < MAX_CHK; i += blockDim.x) g_chunk_expert[i] = -1;
    __syncthreads();

    if (tid == 0) {
        int s = 0;
        for (int e = 0; e < NEXP; e++) {
            offs[e] = s;
            s += (hist[e] + NODES_PER_CHUNK - 1) & ~(NODES_PER_CHUNK - 1);
        }
        offs[NEXP] = s;
    }
    __syncthreads();
    if (tid < NEXP) {
        cursor[tid] = offs[tid];
        int c0 = offs[tid] / NODES_PER_CHUNK;
        int c1 = offs[tid + 1] / NODES_PER_CHUNK;
        for (int c = c0; c < c1; c++) g_chunk_expert[c] = tid;
    }
    __syncthreads();

    for (int n = tid; n < N_NODES; n += blockDim.x) {
        int e = is64 ? (int)sel64[n] : sel32[n];
        int pos = atomicAdd(&cursor[e], 1);
        g_sorted[pos] = n;
    }
}

// ---------------------------------------------------------------------------
// tf32 helpers
// ---------------------------------------------------------------------------
__device__ __forceinline__ unsigned f2tf32(float f) {
    unsigned u;
    asm("cvt.rna.tf32.f32 %0, %1;" : "=r"(u) : "f"(f));
    return u;
}

__device__ __forceinline__ void mma_tf32(float* d, const unsigned* a, const unsigned* b) {
    asm volatile(
        "mma.sync.aligned.m16n8k8.row.col.f32.tf32.tf32.f32 "
        "{%0,%1,%2,%3}, {%4,%5,%6,%7}, {%8,%9}, {%0,%1,%2,%3};\n"
        : "+f"(d[0]), "+f"(d[1]), "+f"(d[2]), "+f"(d[3])
        : "r"(a[0]), "r"(a[1]), "r"(a[2]), "r"(a[3]),
          "r"(b[0]), "r"(b[1]));
}

// Swizzled smem word offset: rows of 64 words, XOR low bits of row into col.
// Keeps float4 groups contiguous (swizzle bits are [2:4]); conflict-free for
// both A-style (stride-1 row) and B-style (stride-8 row) fragment reads.
__device__ __forceinline__ int sw(int row, int col) {
    return row * KT + (col ^ ((row & 7) << 2));
}

// ---------------------------------------------------------------------------
// Kernel 2: grouped GEMM, tf32 tensor cores.
// CTA tile M=128 (16 nodes x 8 batch) x N=128, K in 2 tiles of 64.
// 8 warps in 4x2 grid, each warp 32(M) x 64(N) via m16n8k8 mma.
// ---------------------------------------------------------------------------
extern __shared__ unsigned smem_u[];

__global__ __launch_bounds__(256, 2)
void grouped_gemm_kernel(const float* __restrict__ x,
                         const float* __restrict__ W,
                         float* __restrict__ out) {
    const int e = g_chunk_expert[blockIdx.x];
    if (e < 0) return;

    unsigned* Xs = smem_u;                 // [128][64] swizzled
    unsigned* Ws = smem_u + 128 * KT;      // [128][64] swizzled (row = out ch)
    __shared__ int snode[NODES_PER_CHUNK];

    const int tid  = threadIdx.x;
    const int lane = tid & 31;
    const int warp = tid >> 5;
    const int g    = lane >> 2;   // group 0..7
    const int c    = lane & 3;    // thread-in-group 0..3
    const int mbase = (warp & 3) * 32;   // warp M offset
    const int nbase = (warp >> 2) * 64;  // warp N offset

    if (tid < NODES_PER_CHUNK)
        snode[tid] = g_sorted[blockIdx.x * NODES_PER_CHUNK + tid];
    __syncthreads();

    const float* We = W + (size_t)e * CH * CH;

    float acc[2][8][4];
#pragma unroll
    for (int mt = 0; mt < 2; mt++)
#pragma unroll
        for (int nt = 0; nt < 8; nt++)
#pragma unroll
            for (int i = 0; i < 4; i++) acc[mt][nt][i] = 0.0f;

    for (int k0 = 0; k0 < CH; k0 += KT) {
        // ---- load k-tile into smem (tf32-converted, swizzled) ----
#pragma unroll
        for (int it = 0; it < 8; it++) {
            int idx = tid + it * 256;        // 0..2047
            int row = idx >> 4;              // 0..127
            int q   = (idx & 15) * 4;        // 0,4,...,60

            // X row: node slot = row/8, batch = row%8
            int node = snode[row >> 3];
            float4 v = make_float4(0.f, 0.f, 0.f, 0.f);
            if (node >= 0)
                v = *(const float4*)(x + ((size_t)(row & 7) * N_NODES + node) * CH + k0 + q);
            int xo = sw(row, q);
            Xs[xo + 0] = f2tf32(v.x); Xs[xo + 1] = f2tf32(v.y);
            Xs[xo + 2] = f2tf32(v.z); Xs[xo + 3] = f2tf32(v.w);

            float4 w = *(const float4*)(We + (size_t)row * CH + k0 + q);
            int wo = sw(row, q);
            Ws[wo + 0] = f2tf32(w.x); Ws[wo + 1] = f2tf32(w.y);
            Ws[wo + 2] = f2tf32(w.z); Ws[wo + 3] = f2tf32(w.w);
        }
        __syncthreads();

        // ---- tensor-core compute over this k-tile ----
#pragma unroll
        for (int ks = 0; ks < KT; ks += 8) {
            unsigned a[2][4], b[8][2];
#pragma unroll
            for (int mt = 0; mt < 2; mt++) {
                int r = mbase + mt * 16 + g;
                a[mt][0] = Xs[sw(r,     ks + c)];
                a[mt][1] = Xs[sw(r + 8, ks + c)];
                a[mt][2] = Xs[sw(r,     ks + c + 4)];
                a[mt][3] = Xs[sw(r + 8, ks + c + 4)];
            }
#pragma unroll
            for (int nt = 0; nt < 8; nt++) {
                int rn = nbase + nt * 8 + g;
                b[nt][0] = Ws[sw(rn, ks + c)];
                b[nt][1] = Ws[sw(rn, ks + c + 4)];
            }
#pragma unroll
            for (int mt = 0; mt < 2; mt++)
#pragma unroll
                for (int nt = 0; nt < 8; nt++)
                    mma_tf32(acc[mt][nt], a[mt], b[nt]);
        }
        __syncthreads();
    }

    // ---- store: acc[mt][nt][{0,1}] -> row mbase+mt*16+g, cols 2c,2c+1
    //             acc[mt][nt][{2,3}] -> row +8
#pragma unroll
    for (int mt = 0; mt < 2; mt++) {
#pragma unroll
        for (int half = 0; half < 2; half++) {
            int r = mbase + mt * 16 + g + half * 8;
            int node = snode[r >> 3];
            if (node < 0) continue;
            float* o = out + ((size_t)(r & 7) * N_NODES + node) * CH + nbase;
#pragma unroll
            for (int nt = 0; nt < 8; nt++) {
                float2 v2 = make_float2(acc[mt][nt][half * 2], acc[mt][nt][half * 2 + 1]);
                *(float2*)(o + nt * 8 + c * 2) = v2;
            }
        }
    }
}

// ---------------------------------------------------------------------------
extern "C" void kernel_launch(void* const* d_in, const int* in_sizes, int n_in,
                              void* d_out, int out_size) {
    const float*     x   = (const float*)d_in[0];
    const long long* sel = (const long long*)d_in[1];
    const float*     W   = (const float*)d_in[2];
    float*           out = (float*)d_out;

    static bool attr_set = false;
    if (!attr_set) {
        cudaFuncSetAttribute(grouped_gemm_kernel,
                             cudaFuncAttributeMaxDynamicSharedMemorySize,
                             2 * 128 * KT * (int)sizeof(unsigned));
        attr_set = true;
    }

    sort_nodes_kernel<<<1, 1024>>>(sel);
    grouped_gemm_kernel<<<MAX_CHK, 256, 2 * 128 * KT * sizeof(unsigned)>>>(x, W, out);
}